// round 1
// baseline (speedup 1.0000x reference)
#include <cuda_runtime.h>
#include <math.h>

#define Nn 64
#define Tt 800
#define Hh 512
#define H2 1024
#define G3 3072
#define Oo 80
#define Rr 2

// ---------------- scratch (device globals; no allocation) ----------------
__device__ float g_pre1[Nn * H2];
__device__ float g_pre2[Nn * Hh];
__device__ float g_gi[Nn * G3];
__device__ float g_gh[Nn * G3];
__device__ float g_dec_proj[Nn * H2];
__device__ float g_score[Nn * Tt];
__device__ float g_invsum[Nn];
__device__ float g_dec_in[Nn * 2 * H2];
__device__ float g_partial[8 * Nn * H2];
__device__ float g_residual[Nn * H2];

// ---------------- skinny GEMM: out[64, M] = X[64, K] @ W[M, K]^T + b ----------------
// Block: 256 threads; tile = 32 output columns x 64 rows. Each weight row read
// by exactly one block (W traffic = |W| bytes total).
__global__ void gemm64(const float* __restrict__ X, int ldx,
                       const float* __restrict__ W,
                       const float* __restrict__ bias,
                       float* __restrict__ out, int ldo,
                       int K, int M, int relu)
{
    __shared__ float xs[64][32];
    const int tid = threadIdx.x;
    const int col = blockIdx.x * 32 + (tid & 31);
    const int rg  = tid >> 5;              // 0..7 -> rows rg*8 .. rg*8+7
    float acc[8];
#pragma unroll
    for (int i = 0; i < 8; i++) acc[i] = 0.f;

    const float* wrow = W + (size_t)col * K;

    for (int k0 = 0; k0 < K; k0 += 32) {
        const int rem = K - k0;
        {   // stage X[0:64][k0:k0+32] into smem (8 elems/thread)
            const int base = tid * 8;
            const int r  = base >> 5;
            const int kk = base & 31;
            const float* xp = X + (size_t)r * ldx + k0 + kk;
            if (rem >= 32) {
                float4 v0 = *(const float4*)(xp);
                float4 v1 = *(const float4*)(xp + 4);
                xs[r][kk+0]=v0.x; xs[r][kk+1]=v0.y; xs[r][kk+2]=v0.z; xs[r][kk+3]=v0.w;
                xs[r][kk+4]=v1.x; xs[r][kk+5]=v1.y; xs[r][kk+6]=v1.z; xs[r][kk+7]=v1.w;
            } else {
#pragma unroll
                for (int j = 0; j < 8; j++)
                    xs[r][kk+j] = (kk + j < rem) ? xp[j] : 0.f;
            }
        }
        __syncthreads();

        if (col < M) {
            float w[32];
            if (rem >= 32) {
#pragma unroll
                for (int j = 0; j < 8; j++) {
                    float4 wv = *(const float4*)(wrow + k0 + j*4);
                    w[j*4+0]=wv.x; w[j*4+1]=wv.y; w[j*4+2]=wv.z; w[j*4+3]=wv.w;
                }
            } else {
#pragma unroll
                for (int j = 0; j < 32; j++)
                    w[j] = (j < rem) ? wrow[k0 + j] : 0.f;
            }
#pragma unroll
            for (int kk = 0; kk < 32; kk++) {
                const float wv = w[kk];
#pragma unroll
                for (int rr = 0; rr < 8; rr++)
                    acc[rr] = fmaf(xs[rg*8+rr][kk], wv, acc[rr]);
            }
        }
        __syncthreads();
    }

    if (col < M) {
        const float b = bias[col];
#pragma unroll
        for (int rr = 0; rr < 8; rr++) {
            float v = acc[rr] + b;
            if (relu) v = fmaxf(v, 0.f);
            out[(size_t)(rg*8+rr) * ldo + col] = v;
        }
    }
}

// ---------------- GRU pointwise combine (gates r,z,n) ----------------
// hout: [64,1024]; optional hout2 = dec_in base (writes second half);
// optional resout = resin + h (in-place safe).
__global__ void gru_k(const float* __restrict__ gi, const float* __restrict__ gh,
                      const float* __restrict__ hprev,
                      float* __restrict__ hout,
                      float* __restrict__ hout2,
                      const float* __restrict__ resin,
                      float* __restrict__ resout)
{
    const int idx = blockIdx.x * 256 + threadIdx.x;    // 0..65535
    const int n = idx >> 10, h = idx & (H2 - 1);
    const size_t gb = (size_t)n * G3 + h;
    const float ir = gi[gb], iz = gi[gb + H2], inn = gi[gb + 2*H2];
    const float hr = gh[gb], hz = gh[gb + H2], hn  = gh[gb + 2*H2];
    const float r  = 1.f / (1.f + expf(-(ir + hr)));
    const float z  = 1.f / (1.f + expf(-(iz + hz)));
    const float nn = tanhf(inn + r * hn);
    const float hp = hprev[(size_t)n * H2 + h];
    const float hv = (1.f - z) * nn + z * hp;
    hout[(size_t)n * H2 + h] = hv;
    if (hout2) hout2[(size_t)n * 2 * H2 + H2 + h] = hv;
    if (resin) resout[(size_t)n * H2 + h] = resin[(size_t)n * H2 + h] + hv;
}

// ---------------- attention: scores (one warp per timestep) ----------------
__global__ void attn_score_k(const float* __restrict__ attW,
                             const float* __restrict__ dec_proj,
                             const float* __restrict__ Wattn,
                             const float* __restrict__ b_attn,
                             const int* __restrict__ lengths,
                             float* __restrict__ score)
{
    __shared__ float dp[H2];
    __shared__ float wa[H2];
    const int n = blockIdx.y;
    const int tid = threadIdx.x;
    {
        const int h = tid * 4;
        *(float4*)&dp[h] = *(const float4*)&dec_proj[(size_t)n * H2 + h];
        *(float4*)&wa[h] = *(const float4*)&Wattn[h];
    }
    __syncthreads();
    const int warp = tid >> 5, lane = tid & 31;
    const int t = blockIdx.x * 8 + warp;
    const float* a = attW + ((size_t)n * Tt + t) * H2;
    float s = 0.f;
#pragma unroll
    for (int i = 0; i < 8; i++) {
        const int h = i * 128 + lane * 4;
        float4 v = *(const float4*)&a[h];
        s += tanhf(v.x + dp[h+0]) * wa[h+0];
        s += tanhf(v.y + dp[h+1]) * wa[h+1];
        s += tanhf(v.z + dp[h+2]) * wa[h+2];
        s += tanhf(v.w + dp[h+3]) * wa[h+3];
    }
#pragma unroll
    for (int o = 16; o > 0; o >>= 1) s += __shfl_xor_sync(0xffffffffu, s, o);
    if (lane == 0)
        score[(size_t)n * Tt + t] = (t < lengths[n]) ? expf(s + b_attn[0]) : 0.f;
}

// ---------------- attention: 1/sum per row ----------------
__global__ void attn_sum_k(const float* __restrict__ score, float* __restrict__ invsum)
{
    const int n = blockIdx.x;
    float s = 0.f;
    for (int t = threadIdx.x; t < Tt; t += 256) s += score[(size_t)n * Tt + t];
    __shared__ float red[8];
#pragma unroll
    for (int o = 16; o > 0; o >>= 1) s += __shfl_xor_sync(0xffffffffu, s, o);
    if ((threadIdx.x & 31) == 0) red[threadIdx.x >> 5] = s;
    __syncthreads();
    if (threadIdx.x == 0) {
        float tot = 0.f;
#pragma unroll
        for (int i = 0; i < 8; i++) tot += red[i];
        invsum[n] = 1.f / fmaxf(tot, 1e-12f);
    }
}

// ---------------- attention: weighted sum over T (split 8, deterministic) ----------------
__global__ void attn_apply_k(const float* __restrict__ enc,
                             const float* __restrict__ score,
                             const float* __restrict__ invsum,
                             float* __restrict__ partial)
{
    const int n = blockIdx.y;
    const int sp = blockIdx.x;                  // 0..7, 100 timesteps each
    const int h = threadIdx.x * 4;
    __shared__ float sc[100];
    if (threadIdx.x < 100) sc[threadIdx.x] = score[(size_t)n * Tt + sp * 100 + threadIdx.x];
    __syncthreads();
    float4 acc = make_float4(0.f, 0.f, 0.f, 0.f);
    const float* ep = enc + ((size_t)n * Tt + sp * 100) * H2 + h;
#pragma unroll 4
    for (int t = 0; t < 100; t++) {
        const float w = sc[t];
        float4 v = *(const float4*)(ep + (size_t)t * H2);
        acc.x = fmaf(w, v.x, acc.x);
        acc.y = fmaf(w, v.y, acc.y);
        acc.z = fmaf(w, v.z, acc.z);
        acc.w = fmaf(w, v.w, acc.w);
    }
    const float inv = invsum[n];
    acc.x *= inv; acc.y *= inv; acc.z *= inv; acc.w *= inv;
    *(float4*)&partial[((size_t)sp * Nn + n) * H2 + h] = acc;
}

__global__ void attn_reduce_k(const float* __restrict__ partial, float* __restrict__ dec_in)
{
    const int n = blockIdx.x;
    const int h = threadIdx.x * 4;
    float4 acc = make_float4(0.f, 0.f, 0.f, 0.f);
#pragma unroll
    for (int sp = 0; sp < 8; sp++) {
        float4 v = *(const float4*)&partial[((size_t)sp * Nn + n) * H2 + h];
        acc.x += v.x; acc.y += v.y; acc.z += v.z; acc.w += v.w;
    }
    *(float4*)&dec_in[(size_t)n * 2 * H2 + h] = acc;
}

// ---------------- host-side orchestration ----------------
extern "C" void kernel_launch(void* const* d_in, const int* in_sizes, int n_in,
                              void* d_out, int out_size)
{
    const float* input_enc      = (const float*)d_in[0];
    const float* input_attW_enc = (const float*)d_in[1];
    const float* input_dec      = (const float*)d_in[2];
    const int*   lengths_enc    = (const int*)  d_in[3];
    const float* hidden_att     = (const float*)d_in[4];
    const float* hidden_dec1    = (const float*)d_in[5];
    const float* hidden_dec2    = (const float*)d_in[6];
    const float* W_pre1 = (const float*)d_in[7];
    const float* b_pre1 = (const float*)d_in[8];
    const float* W_pre2 = (const float*)d_in[9];
    const float* b_pre2 = (const float*)d_in[10];
    const float* Wih_att = (const float*)d_in[11];
    const float* Whh_att = (const float*)d_in[12];
    const float* bih_att = (const float*)d_in[13];
    const float* bhh_att = (const float*)d_in[14];
    const float* W_ld   = (const float*)d_in[15];
    const float* b_ld   = (const float*)d_in[16];
    const float* W_attn = (const float*)d_in[17];
    const float* b_attn = (const float*)d_in[18];
    const float* W_sc   = (const float*)d_in[19];
    const float* b_sc   = (const float*)d_in[20];
    const float* Wih_d1 = (const float*)d_in[21];
    const float* Whh_d1 = (const float*)d_in[22];
    const float* bih_d1 = (const float*)d_in[23];
    const float* bhh_d1 = (const float*)d_in[24];
    const float* Wih_d2 = (const float*)d_in[25];
    const float* Whh_d2 = (const float*)d_in[26];
    const float* bih_d2 = (const float*)d_in[27];
    const float* bhh_d2 = (const float*)d_in[28];
    const float* W_out  = (const float*)d_in[29];
    const float* b_out  = (const float*)d_in[30];

    float *pre1, *pre2, *gi, *gh, *dec_proj, *score, *invsum, *dec_in, *partial, *residual;
    cudaGetSymbolAddress((void**)&pre1,     g_pre1);
    cudaGetSymbolAddress((void**)&pre2,     g_pre2);
    cudaGetSymbolAddress((void**)&gi,       g_gi);
    cudaGetSymbolAddress((void**)&gh,       g_gh);
    cudaGetSymbolAddress((void**)&dec_proj, g_dec_proj);
    cudaGetSymbolAddress((void**)&score,    g_score);
    cudaGetSymbolAddress((void**)&invsum,   g_invsum);
    cudaGetSymbolAddress((void**)&dec_in,   g_dec_in);
    cudaGetSymbolAddress((void**)&partial,  g_partial);
    cudaGetSymbolAddress((void**)&residual, g_residual);

    float* out       = (float*)d_out;                 // [64, 2, 80]
    float* h_att_out = out + Nn * Rr * Oo;            // [64, 1024]
    float* h_d1_out  = h_att_out + Nn * H2;
    float* h_d2_out  = h_d1_out + Nn * H2;

    // prenet
    gemm64<<<H2/32, 256>>>(input_dec, Oo, W_pre1, b_pre1, pre1, H2, Oo, H2, 1);
    gemm64<<<Hh/32, 256>>>(pre1, H2, W_pre2, b_pre2, pre2, Hh, H2, Hh, 1);
    // attention GRU
    gemm64<<<G3/32, 256>>>(pre2, Hh, Wih_att, bih_att, gi, G3, Hh, G3, 0);
    gemm64<<<G3/32, 256>>>(hidden_att, H2, Whh_att, bhh_att, gh, G3, H2, G3, 0);
    gru_k<<<256, 256>>>(gi, gh, hidden_att, h_att_out, dec_in, nullptr, nullptr);
    // additive attention
    gemm64<<<H2/32, 256>>>(h_att_out, H2, W_ld, b_ld, dec_proj, H2, H2, H2, 0);
    {
        dim3 gs(Tt/8, Nn);
        attn_score_k<<<gs, 256>>>(input_attW_enc, dec_proj, W_attn, b_attn, lengths_enc, score);
    }
    attn_sum_k<<<Nn, 256>>>(score, invsum);
    {
        dim3 ga(8, Nn);
        attn_apply_k<<<ga, 256>>>(input_enc, score, invsum, partial);
    }
    attn_reduce_k<<<Nn, 256>>>(partial, dec_in);
    // decoder stack
    gemm64<<<H2/32, 256>>>(dec_in, 2*H2, W_sc, b_sc, residual, H2, 2*H2, H2, 0);
    gemm64<<<G3/32, 256>>>(dec_in, 2*H2, Wih_d1, bih_d1, gi, G3, 2*H2, G3, 0);
    gemm64<<<G3/32, 256>>>(hidden_dec1, H2, Whh_d1, bhh_d1, gh, G3, H2, G3, 0);
    gru_k<<<256, 256>>>(gi, gh, hidden_dec1, h_d1_out, nullptr, residual, residual);
    gemm64<<<G3/32, 256>>>(residual, H2, Wih_d2, bih_d2, gi, G3, H2, G3, 0);
    gemm64<<<G3/32, 256>>>(hidden_dec2, H2, Whh_d2, bhh_d2, gh, G3, H2, G3, 0);
    gru_k<<<256, 256>>>(gi, gh, hidden_dec2, h_d2_out, nullptr, residual, residual);
    // output projection: [64, 160] contiguous == [64, 2, 80]
    gemm64<<<(Rr*Oo)/32, 256>>>(residual, H2, W_out, b_out, out, Rr*Oo, H2, Rr*Oo, 0);
}

// round 2
// speedup vs baseline: 2.5790x; 2.5790x over previous
#include <cuda_runtime.h>
#include <math.h>

#define Nn 64
#define Tt 800
#define Hh 512
#define H2 1024
#define G3 3072
#define Oo 80
#define Rr 2
#define ASPLIT 16

// ---------------- scratch (device globals; no allocation) ----------------
__device__ float g_pre1[Nn * H2];
__device__ float g_pre2[Nn * Hh];
__device__ float g_dec_proj[Nn * H2];
__device__ float g_score[Nn * Tt];
__device__ float g_invsum[Nn];
__device__ float g_dec_in[Nn * 2 * H2];
__device__ float g_residual[Nn * H2];
__device__ float g_part_gi[8 * Nn * G3];
__device__ float g_part_gh[8 * Nn * G3];
__device__ float g_part_sc[8 * Nn * H2];
__device__ float g_part_x[8 * Nn * H2];
__device__ float g_attn_part[ASPLIT * Nn * H2];

// ---------------- batched split-K skinny GEMM ----------------
// partial[sp][64][M] += X[64, kchunk] @ W[M, kchunk]^T  (no bias here)
// block: 256 threads = 32 cols x 8 row-groups (8 rows each, as 4 row-pairs).
struct GP {
    const float* X; const float* W; float* P;
    int ldx; int K; int M; int SK;
};

__device__ __forceinline__ void ffma2(unsigned long long& d,
                                      unsigned long long a,
                                      unsigned long long b)
{
    asm("fma.rn.f32x2 %0, %1, %2, %0;" : "+l"(d) : "l"(a), "l"(b));
}

__global__ void __launch_bounds__(256) gemm_sk(GP p0, GP p1, GP p2, int n0, int n01)
{
    GP p; int lb;
    {
        const int bid = blockIdx.x;
        if (bid < n0)        { p = p0; lb = bid; }
        else if (bid < n01)  { p = p1; lb = bid - n0; }
        else                 { p = p2; lb = bid - n01; }
    }
    const int cb   = p.M >> 5;          // column-blocks
    const int colb = lb % cb;
    const int sp   = lb / cb;
    const int kc   = p.K / p.SK;
    const int kbeg = sp * kc;
    const int kend = kbeg + kc;

    __shared__ __align__(16) float sx[32 * 66];   // sx[kk*66 + row], row-pairs 8B aligned
    const int tid = threadIdx.x;
    const int col = colb * 32 + (tid & 31);
    const int rg  = tid >> 5;                     // 0..7 -> rows rg*8..rg*8+7

    unsigned long long acc2[4] = {0ull, 0ull, 0ull, 0ull};
    const float* wrow = p.W + (size_t)col * p.K;

    for (int k0 = kbeg; k0 < kend; k0 += 32) {
        const int rem = kend - k0;
        {   // stage X[0:64][k0:k0+32] pair-packed: sx[kk*66 + r]
            const int base = tid * 8;
            const int r  = base >> 5;
            const int kk = base & 31;
            const float* xp = p.X + (size_t)r * p.ldx + k0 + kk;
            if (rem >= 32) {
                float4 v0 = *(const float4*)(xp);
                float4 v1 = *(const float4*)(xp + 4);
                sx[(kk+0)*66 + r] = v0.x; sx[(kk+1)*66 + r] = v0.y;
                sx[(kk+2)*66 + r] = v0.z; sx[(kk+3)*66 + r] = v0.w;
                sx[(kk+4)*66 + r] = v1.x; sx[(kk+5)*66 + r] = v1.y;
                sx[(kk+6)*66 + r] = v1.z; sx[(kk+7)*66 + r] = v1.w;
            } else {
#pragma unroll
                for (int j = 0; j < 8; j++)
                    sx[(kk+j)*66 + r] = (kk + j < rem) ? xp[j] : 0.f;
            }
        }
        __syncthreads();

        float w[32];
        if (rem >= 32) {
#pragma unroll
            for (int j = 0; j < 8; j++) {
                float4 wv = *(const float4*)(wrow + k0 + j*4);
                w[j*4+0]=wv.x; w[j*4+1]=wv.y; w[j*4+2]=wv.z; w[j*4+3]=wv.w;
            }
        } else {
#pragma unroll
            for (int j = 0; j < 32; j++)
                w[j] = (j < rem) ? wrow[k0 + j] : 0.f;
        }
#pragma unroll
        for (int kk = 0; kk < 32; kk++) {
            unsigned long long w2;
            asm("mov.b64 %0, {%1, %2};" : "=l"(w2) : "f"(w[kk]), "f"(w[kk]));
#pragma unroll
            for (int q = 0; q < 4; q++) {
                const int rp = rg * 4 + q;
                unsigned long long xv =
                    *reinterpret_cast<const unsigned long long*>(&sx[kk*66 + 2*rp]);
                ffma2(acc2[q], xv, w2);
            }
        }
        __syncthreads();
    }

#pragma unroll
    for (int q = 0; q < 4; q++) {
        const int rp = rg * 4 + q;
        const unsigned int lo = (unsigned int)(acc2[q] & 0xffffffffull);
        const unsigned int hi = (unsigned int)(acc2[q] >> 32);
        p.P[((size_t)(sp*64 + 2*rp    )) * p.M + col] = __uint_as_float(lo);
        p.P[((size_t)(sp*64 + 2*rp + 1)) * p.M + col] = __uint_as_float(hi);
    }
}

// ---------------- standalone partial reduce: out = sum(P) + bias (opt relu) ----------------
__global__ void reduce_k(const float* __restrict__ P, float* __restrict__ out,
                         const float* __restrict__ bias, int M, int SK, int relu)
{
    const int idx = blockIdx.x * 256 + threadIdx.x;
    const int r = idx / M, col = idx % M;
    float s = bias[col];
    for (int sp = 0; sp < SK; sp++) s += P[((size_t)(sp*64 + r)) * M + col];
    if (relu) s = fmaxf(s, 0.f);
    out[(size_t)r * M + col] = s;
}

// ---------------- GRU combine with fused split-K reduce ----------------
__global__ void gru_k(const float* __restrict__ giP, int skGi,
                      const float* __restrict__ ghP, int skGh,
                      const float* __restrict__ bih, const float* __restrict__ bhh,
                      const float* __restrict__ hprev,
                      float* __restrict__ hout, float* __restrict__ hout2,
                      const float* __restrict__ scP, int skSc,
                      const float* __restrict__ b_sc,
                      const float* __restrict__ resin, float* __restrict__ resout)
{
    const int idx = blockIdx.x * 256 + threadIdx.x;    // 0..65535
    const int n = idx >> 10, h = idx & (H2 - 1);
    float ir = bih[h], iz = bih[h + H2], inn = bih[h + 2*H2];
    for (int sp = 0; sp < skGi; sp++) {
        const size_t b = ((size_t)(sp*64 + n)) * G3 + h;
        ir += giP[b]; iz += giP[b + H2]; inn += giP[b + 2*H2];
    }
    float hr = bhh[h], hz = bhh[h + H2], hn = bhh[h + 2*H2];
    for (int sp = 0; sp < skGh; sp++) {
        const size_t b = ((size_t)(sp*64 + n)) * G3 + h;
        hr += ghP[b]; hz += ghP[b + H2]; hn += ghP[b + 2*H2];
    }
    const float r  = 1.f / (1.f + expf(-(ir + hr)));
    const float z  = 1.f / (1.f + expf(-(iz + hz)));
    const float nn = tanhf(inn + r * hn);
    const float hp = hprev[(size_t)n * H2 + h];
    const float hv = (1.f - z) * nn + z * hp;
    hout[(size_t)n * H2 + h] = hv;
    if (hout2) hout2[(size_t)n * 2 * H2 + H2 + h] = hv;
    if (scP) {
        float rv = b_sc[h];
        for (int sp = 0; sp < skSc; sp++)
            rv += scP[((size_t)(sp*64 + n)) * H2 + h];
        resout[(size_t)n * H2 + h] = rv + hv;
    } else if (resin) {
        resout[(size_t)n * H2 + h] = resin[(size_t)n * H2 + h] + hv;
    }
}

// ---------------- attention: scores (one warp per timestep, length early-out) ----------------
__global__ void attn_score_k(const float* __restrict__ attW,
                             const float* __restrict__ dec_proj,
                             const float* __restrict__ Wattn,
                             const float* __restrict__ b_attn,
                             const int* __restrict__ lengths,
                             float* __restrict__ score)
{
    __shared__ float dp[H2];
    __shared__ float wa[H2];
    const int n = blockIdx.y;
    const int tid = threadIdx.x;
    {
        const int h = tid * 4;
        *(float4*)&dp[h] = *(const float4*)&dec_proj[(size_t)n * H2 + h];
        *(float4*)&wa[h] = *(const float4*)&Wattn[h];
    }
    __syncthreads();
    const int warp = tid >> 5, lane = tid & 31;
    const int t = blockIdx.x * 8 + warp;
    const int len = lengths[n];
    if (t >= len) {                       // uniform per warp; no barriers below
        if (lane == 0) score[(size_t)n * Tt + t] = 0.f;
        return;
    }
    const float* a = attW + ((size_t)n * Tt + t) * H2;
    float s = 0.f;
#pragma unroll
    for (int i = 0; i < 8; i++) {
        const int h = i * 128 + lane * 4;
        float4 v = *(const float4*)&a[h];
        s += tanhf(v.x + dp[h+0]) * wa[h+0];
        s += tanhf(v.y + dp[h+1]) * wa[h+1];
        s += tanhf(v.z + dp[h+2]) * wa[h+2];
        s += tanhf(v.w + dp[h+3]) * wa[h+3];
    }
#pragma unroll
    for (int o = 16; o > 0; o >>= 1) s += __shfl_xor_sync(0xffffffffu, s, o);
    if (lane == 0) score[(size_t)n * Tt + t] = expf(s + b_attn[0]);
}

// ---------------- attention: 1/sum per row ----------------
__global__ void attn_sum_k(const float* __restrict__ score, float* __restrict__ invsum)
{
    const int n = blockIdx.x;
    float s = 0.f;
    for (int t = threadIdx.x; t < Tt; t += 256) s += score[(size_t)n * Tt + t];
    __shared__ float red[8];
#pragma unroll
    for (int o = 16; o > 0; o >>= 1) s += __shfl_xor_sync(0xffffffffu, s, o);
    if ((threadIdx.x & 31) == 0) red[threadIdx.x >> 5] = s;
    __syncthreads();
    if (threadIdx.x == 0) {
        float tot = 0.f;
#pragma unroll
        for (int i = 0; i < 8; i++) tot += red[i];
        invsum[n] = 1.f / fmaxf(tot, 1e-12f);
    }
}

// ---------------- attention: weighted sum over T (split 16, deterministic) ----------------
__global__ void attn_apply_k(const float* __restrict__ enc,
                             const float* __restrict__ score,
                             const float* __restrict__ invsum,
                             float* __restrict__ partial)
{
    const int n = blockIdx.y;
    const int sp = blockIdx.x;                  // 0..15, 50 timesteps each
    const int h = threadIdx.x * 4;
    __shared__ float sc[50];
    if (threadIdx.x < 50) sc[threadIdx.x] = score[(size_t)n * Tt + sp * 50 + threadIdx.x];
    __syncthreads();
    float4 acc = make_float4(0.f, 0.f, 0.f, 0.f);
    const float* ep = enc + ((size_t)n * Tt + sp * 50) * H2 + h;
#pragma unroll 2
    for (int t = 0; t < 50; t++) {
        const float w = sc[t];
        if (w != 0.f) {                          // uniform across block
            float4 v = *(const float4*)(ep + (size_t)t * H2);
            acc.x = fmaf(w, v.x, acc.x);
            acc.y = fmaf(w, v.y, acc.y);
            acc.z = fmaf(w, v.z, acc.z);
            acc.w = fmaf(w, v.w, acc.w);
        }
    }
    const float inv = invsum[n];
    acc.x *= inv; acc.y *= inv; acc.z *= inv; acc.w *= inv;
    *(float4*)&partial[((size_t)sp * Nn + n) * H2 + h] = acc;
}

__global__ void attn_reduce_k(const float* __restrict__ partial, float* __restrict__ dec_in)
{
    const int n = blockIdx.x;
    const int h = threadIdx.x * 4;
    float4 acc = make_float4(0.f, 0.f, 0.f, 0.f);
#pragma unroll
    for (int sp = 0; sp < ASPLIT; sp++) {
        float4 v = *(const float4*)&partial[((size_t)sp * Nn + n) * H2 + h];
        acc.x += v.x; acc.y += v.y; acc.z += v.z; acc.w += v.w;
    }
    *(float4*)&dec_in[(size_t)n * 2 * H2 + h] = acc;
}

// ---------------- host-side orchestration ----------------
static inline GP mkgp(const float* X, int ldx, const float* W, float* P, int K, int M, int SK)
{
    GP g; g.X = X; g.ldx = ldx; g.W = W; g.P = P; g.K = K; g.M = M; g.SK = SK; return g;
}
static inline int nblk(const GP& g) { return (g.M >> 5) * g.SK; }

static inline void launch1(const GP& a) {
    int n = nblk(a);
    gemm_sk<<<n, 256>>>(a, a, a, n, n);
}
static inline void launch2(const GP& a, const GP& b) {
    int na = nblk(a), nb = nblk(b);
    gemm_sk<<<na + nb, 256>>>(a, b, b, na, na + nb);
}
static inline void launch3(const GP& a, const GP& b, const GP& c) {
    int na = nblk(a), nb = nblk(b), nc = nblk(c);
    gemm_sk<<<na + nb + nc, 256>>>(a, b, c, na, na + nb);
}

extern "C" void kernel_launch(void* const* d_in, const int* in_sizes, int n_in,
                              void* d_out, int out_size)
{
    const float* input_enc      = (const float*)d_in[0];
    const float* input_attW_enc = (const float*)d_in[1];
    const float* input_dec      = (const float*)d_in[2];
    const int*   lengths_enc    = (const int*)  d_in[3];
    const float* hidden_att     = (const float*)d_in[4];
    const float* hidden_dec1    = (const float*)d_in[5];
    const float* hidden_dec2    = (const float*)d_in[6];
    const float* W_pre1 = (const float*)d_in[7];
    const float* b_pre1 = (const float*)d_in[8];
    const float* W_pre2 = (const float*)d_in[9];
    const float* b_pre2 = (const float*)d_in[10];
    const float* Wih_att = (const float*)d_in[11];
    const float* Whh_att = (const float*)d_in[12];
    const float* bih_att = (const float*)d_in[13];
    const float* bhh_att = (const float*)d_in[14];
    const float* W_ld   = (const float*)d_in[15];
    const float* b_ld   = (const float*)d_in[16];
    const float* W_attn = (const float*)d_in[17];
    const float* b_attn = (const float*)d_in[18];
    const float* W_sc   = (const float*)d_in[19];
    const float* b_sc   = (const float*)d_in[20];
    const float* Wih_d1 = (const float*)d_in[21];
    const float* Whh_d1 = (const float*)d_in[22];
    const float* bih_d1 = (const float*)d_in[23];
    const float* bhh_d1 = (const float*)d_in[24];
    const float* Wih_d2 = (const float*)d_in[25];
    const float* Whh_d2 = (const float*)d_in[26];
    const float* bih_d2 = (const float*)d_in[27];
    const float* bhh_d2 = (const float*)d_in[28];
    const float* W_out  = (const float*)d_in[29];
    const float* b_out  = (const float*)d_in[30];

    float *pre1, *pre2, *dec_proj, *score, *invsum, *dec_in, *residual;
    float *pgi, *pgh, *psc, *ppx, *pattn;
    cudaGetSymbolAddress((void**)&pre1,     g_pre1);
    cudaGetSymbolAddress((void**)&pre2,     g_pre2);
    cudaGetSymbolAddress((void**)&dec_proj, g_dec_proj);
    cudaGetSymbolAddress((void**)&score,    g_score);
    cudaGetSymbolAddress((void**)&invsum,   g_invsum);
    cudaGetSymbolAddress((void**)&dec_in,   g_dec_in);
    cudaGetSymbolAddress((void**)&residual, g_residual);
    cudaGetSymbolAddress((void**)&pgi,      g_part_gi);
    cudaGetSymbolAddress((void**)&pgh,      g_part_gh);
    cudaGetSymbolAddress((void**)&psc,      g_part_sc);
    cudaGetSymbolAddress((void**)&ppx,      g_part_x);
    cudaGetSymbolAddress((void**)&pattn,    g_attn_part);

    float* out       = (float*)d_out;                 // [64, 2, 80]
    float* h_att_out = out + Nn * Rr * Oo;            // [64, 1024]
    float* h_d1_out  = h_att_out + Nn * H2;
    float* h_d2_out  = h_d1_out + Nn * H2;

    // L1: pre1 (independent) + gh_att (independent)
    launch2(mkgp(input_dec, Oo, W_pre1, ppx, Oo, H2, 1),
            mkgp(hidden_att, H2, Whh_att, pgh, H2, G3, 8));
    // L2: reduce pre1 (+relu)
    reduce_k<<<(Nn*H2)/256, 256>>>(ppx, pre1, b_pre1, H2, 1, 1);
    // L3: pre2
    launch1(mkgp(pre1, H2, W_pre2, ppx, H2, Hh, 8));
    reduce_k<<<(Nn*Hh)/256, 256>>>(ppx, pre2, b_pre2, Hh, 8, 1);
    // L5: gi_att
    launch1(mkgp(pre2, Hh, Wih_att, pgi, Hh, G3, 4));
    // L6: attention GRU (fused partial reduce); writes h_att + dec_in[:,H2:]
    gru_k<<<(Nn*H2)/256, 256>>>(pgi, 4, pgh, 8, bih_att, bhh_att, hidden_att,
                                h_att_out, dec_in, nullptr, 0, nullptr,
                                nullptr, nullptr);
    // L7: dec_proj
    launch1(mkgp(h_att_out, H2, W_ld, ppx, H2, H2, 8));
    reduce_k<<<(Nn*H2)/256, 256>>>(ppx, dec_proj, b_ld, H2, 8, 0);
    // attention
    {
        dim3 gs(Tt/8, Nn);
        attn_score_k<<<gs, 256>>>(input_attW_enc, dec_proj, W_attn, b_attn, lengths_enc, score);
    }
    attn_sum_k<<<Nn, 256>>>(score, invsum);
    {
        dim3 ga(ASPLIT, Nn);
        attn_apply_k<<<ga, 256>>>(input_enc, score, invsum, pattn);
    }
    attn_reduce_k<<<Nn, 256>>>(pattn, dec_in);
    // L13: W_sc + gi_d1 + gh_d1 (all independent once dec_in is ready)
    launch3(mkgp(dec_in, 2*H2, W_sc,   psc, 2*H2, H2, 8),
            mkgp(dec_in, 2*H2, Wih_d1, pgi, 2*H2, G3, 8),
            mkgp(hidden_dec1, H2, Whh_d1, pgh, H2, G3, 8));
    // L14: gru1 (fused W_sc reduce + residual)
    gru_k<<<(Nn*H2)/256, 256>>>(pgi, 8, pgh, 8, bih_d1, bhh_d1, hidden_dec1,
                                h_d1_out, nullptr, psc, 8, b_sc,
                                nullptr, residual);
    // L15: gi_d2 + gh_d2
    launch2(mkgp(residual, H2, Wih_d2, pgi, H2, G3, 8),
            mkgp(hidden_dec2, H2, Whh_d2, pgh, H2, G3, 8));
    // L16: gru2 (residual += h)
    gru_k<<<(Nn*H2)/256, 256>>>(pgi, 8, pgh, 8, bih_d2, bhh_d2, hidden_dec2,
                                h_d2_out, nullptr, nullptr, 0, nullptr,
                                residual, residual);
    // L17: output projection [64,160]
    launch1(mkgp(residual, H2, W_out, ppx, H2, Rr*Oo, 8));
    reduce_k<<<(Nn*Rr*Oo)/256, 256>>>(ppx, out, b_out, Rr*Oo, 8, 0);
}